// round 17
// baseline (speedup 1.0000x reference)
#include <cuda_runtime.h>
#include <cuda_bf16.h>
#include <cstdint>

// ---------------------------------------------------------------------------
// RNN: h_t = tanh(x_t @ Wx + h_{t-1} @ Wh),  B=32, L=512, D=1024, fp32.
// Phase 1: xp = x @ Wx via mma.sync 3xTF32 (R14 version: cp.async double-
//          buffered, two syncs per tile, 2 CTAs/SM).
// Phase 2: persistent recurrence, TWO-GROUP INTERLEAVE: each block serves two
//          independent batch groups; each group's barrier wait is hidden
//          behind the other group's compute phase.
// ---------------------------------------------------------------------------

#define B_DIM 32
#define L_DIM 512
#define D_DIM 1024
#define NB 128
#define TPB 256

typedef unsigned long long u64;

__device__ unsigned g_ctrs[4];

__global__ void init_flags_kernel() {
    if (threadIdx.x < 4) g_ctrs[threadIdx.x] = 0u;
}

__device__ __forceinline__ u64 pack2(float lo, float hi) {
    u64 r;
    asm("mov.b64 %0, {%1, %2};" : "=l"(r) : "f"(lo), "f"(hi));
    return r;
}
__device__ __forceinline__ void unpack2(u64 v, float& lo, float& hi) {
    asm("mov.b64 {%0, %1}, %2;" : "=f"(lo), "=f"(hi) : "l"(v));
}
__device__ __forceinline__ void ffma2(u64& d, u64 a, u64 b) {
    asm("fma.rn.f32x2 %0, %1, %2, %0;" : "+l"(d) : "l"(a), "l"(b));
}

// tf32 split: hi = tf32(v), lo = tf32(v - float(hi))
__device__ __forceinline__ void tf32_split(float v, uint32_t& hi, uint32_t& lo) {
    asm("cvt.rna.tf32.f32 %0, %1;" : "=r"(hi) : "f"(v));
    float r = v - __uint_as_float(hi);
    asm("cvt.rna.tf32.f32 %0, %1;" : "=r"(lo) : "f"(r));
}

__device__ __forceinline__ void mma_tf32(float* d, const uint32_t* a, const uint32_t* b) {
    asm("mma.sync.aligned.m16n8k8.row.col.f32.tf32.tf32.f32 "
        "{%0,%1,%2,%3}, {%4,%5,%6,%7}, {%8,%9}, {%0,%1,%2,%3};"
        : "+f"(d[0]), "+f"(d[1]), "+f"(d[2]), "+f"(d[3])
        : "r"(a[0]), "r"(a[1]), "r"(a[2]), "r"(a[3]), "r"(b[0]), "r"(b[1]));
}

__device__ __forceinline__ uint32_t smem_u32p(const void* p) {
    uint32_t a;
    asm("{ .reg .u64 t; cvta.to.shared.u64 t, %1; cvt.u32.u64 %0, t; }" : "=r"(a) : "l"(p));
    return a;
}
__device__ __forceinline__ void cp16(uint32_t dst, const void* src) {
    asm volatile("cp.async.cg.shared.global [%0], [%1], 16;" :: "r"(dst), "l"(src));
}

// ---------------------------------------------------------------------------
// Phase 1 (R14 exact): 3xTF32 mma.sync, cp.async, 2 CTAs/SM, two syncs/tile.
// ---------------------------------------------------------------------------
#define KT 32
#define AST 36
#define BST 136
#define ABUF_F (128 * AST)
#define BBUF_F (KT * BST)
#define P1_SMEM_BYTES ((2 * ABUF_F + 2 * BBUF_F) * 4)

__global__ __launch_bounds__(256, 2) void gemm_mma_kernel(
    const float* __restrict__ A, const float* __restrict__ W,
    float* __restrict__ C)
{
    extern __shared__ __align__(16) float sm1[];
    float* As = sm1;
    float* Bs = sm1 + 2 * ABUF_F;

    const int tid  = threadIdx.x;
    const int warp = tid >> 5;
    const int lane = tid & 31;
    const int wm = warp >> 2;
    const int wn = warp & 3;
    const int m0 = blockIdx.y * 128;
    const int n0 = blockIdx.x * 128;

    const int lr = lane >> 2;
    const int lc = lane & 3;

    const uint32_t asb[2] = { smem_u32p(As), smem_u32p(As + ABUF_F) };
    const uint32_t bsb[2] = { smem_u32p(Bs), smem_u32p(Bs + BBUF_F) };

    const float* aSrc[4];
    const float* bSrc[4];
    uint32_t aOff[4], bOff[4];
#pragma unroll
    for (int it = 0; it < 4; ++it) {
        int idx = it * 256 + tid;
        int r = idx >> 3, k4 = idx & 7;
        aSrc[it] = A + (size_t)(m0 + r) * D_DIM + k4 * 4;
        aOff[it] = (uint32_t)(r * AST + k4 * 4) * 4;
        int kr = idx >> 5, n4 = idx & 31;
        bSrc[it] = W + (size_t)kr * D_DIM + n0 + n4 * 4;
        bOff[it] = (uint32_t)(kr * BST + n4 * 4) * 4;
    }

    float acc[4][4][4];
#pragma unroll
    for (int i = 0; i < 4; ++i)
#pragma unroll
        for (int j = 0; j < 4; ++j)
#pragma unroll
            for (int p = 0; p < 4; ++p) acc[i][j][p] = 0.0f;

    auto issue_tile = [&](int buf) {
#pragma unroll
        for (int it = 0; it < 4; ++it) {
            cp16(asb[buf] + aOff[it], aSrc[it]);
            aSrc[it] += KT;
        }
#pragma unroll
        for (int it = 0; it < 4; ++it) {
            cp16(bsb[buf] + bOff[it], bSrc[it]);
            bSrc[it] += (size_t)KT * D_DIM;
        }
        asm volatile("cp.async.commit_group;");
    };

    issue_tile(0);

    int cur = 0;
    for (int kt = 0; kt < D_DIM / KT; ++kt) {
        const bool more = (kt + 1) < (D_DIM / KT);
        if (more) {
            issue_tile(cur ^ 1);
            asm volatile("cp.async.wait_group 1;");
        } else {
            asm volatile("cp.async.wait_group 0;");
        }
        __syncthreads();

        const float* as = As + cur * ABUF_F;
        const float* bs = Bs + cur * BBUF_F;
#pragma unroll
        for (int ks = 0; ks < 4; ++ks) {
            const int kbase = ks * 8;
            uint32_t ah[4][4], al[4][4];
#pragma unroll
            for (int fm = 0; fm < 4; ++fm) {
                const int rbase = wm * 64 + fm * 16;
                float a0 = as[(rbase + lr) * AST + kbase + lc];
                float a1 = as[(rbase + lr + 8) * AST + kbase + lc];
                float a2 = as[(rbase + lr) * AST + kbase + lc + 4];
                float a3 = as[(rbase + lr + 8) * AST + kbase + lc + 4];
                tf32_split(a0, ah[fm][0], al[fm][0]);
                tf32_split(a1, ah[fm][1], al[fm][1]);
                tf32_split(a2, ah[fm][2], al[fm][2]);
                tf32_split(a3, ah[fm][3], al[fm][3]);
            }
            uint32_t bh[4][2], bl[4][2];
#pragma unroll
            for (int fn = 0; fn < 4; ++fn) {
                const int nbase = wn * 32 + fn * 8;
                float b0 = bs[(kbase + lc) * BST + nbase + lr];
                float b1 = bs[(kbase + lc + 4) * BST + nbase + lr];
                tf32_split(b0, bh[fn][0], bl[fn][0]);
                tf32_split(b1, bh[fn][1], bl[fn][1]);
            }
#pragma unroll
            for (int fm = 0; fm < 4; ++fm)
#pragma unroll
                for (int fn = 0; fn < 4; ++fn) {
                    mma_tf32(acc[fm][fn], ah[fm], bl[fn]);
                    mma_tf32(acc[fm][fn], al[fm], bh[fn]);
                    mma_tf32(acc[fm][fn], ah[fm], bh[fn]);
                }
        }
        __syncthreads();
        cur ^= 1;
    }

#pragma unroll
    for (int fm = 0; fm < 4; ++fm) {
        const int rbase = m0 + wm * 64 + fm * 16 + lr;
#pragma unroll
        for (int fn = 0; fn < 4; ++fn) {
            const int cbase = n0 + wn * 32 + fn * 8 + lc * 2;
            *(float2*)(C + (size_t)rbase * D_DIM + cbase) =
                make_float2(acc[fm][fn][0], acc[fm][fn][1]);
            *(float2*)(C + (size_t)(rbase + 8) * D_DIM + cbase) =
                make_float2(acc[fm][fn][2], acc[fm][fn][3]);
        }
    }
}

// ---------------------------------------------------------------------------
// Phase 2: persistent recurrence, two-group interleave.
// bid -> pair p = bid>>6 serves groups (2p, 2p+1); jg = bid&63 -> 16 columns.
// Thread: jq = lane&7 -> 2 columns per group; kc = warp*4 + (lane>>3) -> 32 k.
// Partial column swizzle kcs = kc ^ (jq & 4) -> conflict-free STS.
// Per group: wait(prev) -> stage -> compute -> reduce/store -> arrive.
// Group A's wait hides behind group B's phase and vice versa.
// ---------------------------------------------------------------------------
#define HROW_F 1152
#define PART_STRIDE 36
#define HS_G_FLOATS (8 * HROW_F)
#define PART_OFF2 (2 * HS_G_FLOATS)
#define PART2_FLOATS (128 * PART_STRIDE)
#define SMEM2_FLOATS (PART_OFF2 + PART2_FLOATS)

__global__ __launch_bounds__(TPB, 1) void rnn_steps_kernel(
    float* __restrict__ out,          // [B, L, D]: holds xp, overwritten by h
    const float* __restrict__ h0,     // [B, D]
    const float* __restrict__ Wh)     // [D, D]
{
    extern __shared__ __align__(16) float smem[];
    float* hsA  = smem;                       // 8 rows
    float* hsB  = smem + HS_G_FLOATS;         // 8 rows
    float* part = smem + PART_OFF2;           // [128][36]

    const int tid  = threadIdx.x;
    const int warp = tid >> 5;
    const int lane = tid & 31;
    const int bid  = blockIdx.x;
    const int pair = bid >> 6;                // 0,1
    const int jg   = bid & 63;
    const int j0   = jg * 16;
    const int gA = pair * 2, gB = pair * 2 + 1;
    const int b0A = gA * 8, b0B = gB * 8;
    const int jq = lane & 7;                  // 2 cols per group
    const int kc = (warp << 2) | (lane >> 3); // 32 k-chunks
    const int kb = kc * 32;
    const int kcs = kc ^ (jq & 4);            // swizzled partial column

    // Wh registers for both groups' column slices (same columns j0+jq*2+jl)
    u64 wreg[2][16];
#pragma unroll
    for (int jl = 0; jl < 2; ++jl) {
        const int jcol = j0 + jq * 2 + jl;
#pragma unroll
        for (int kk = 0; kk < 16; ++kk) {
            float w0 = Wh[(size_t)(kb + 2 * kk)     * D_DIM + jcol];
            float w1 = Wh[(size_t)(kb + 2 * kk + 1) * D_DIM + jcol];
            wreg[jl][kk] = pack2(w0, w1);
        }
    }

    unsigned* ctrA = &g_ctrs[gA];
    unsigned* ctrB = &g_ctrs[gB];

    // reduce/output ownership (threads 0..127): b = tid>>4, j = tid&15
    const int rb = tid >> 4, rj = tid & 15;
    const size_t obaseA = ((size_t)(b0A + rb) * L_DIM) * D_DIM + j0 + rj;
    const size_t obaseB = ((size_t)(b0B + rb) * L_DIM) * D_DIM + j0 + rj;

    float xpA = 0.0f, xpB = 0.0f;
    if (tid < 128) { xpA = out[obaseA]; xpB = out[obaseB]; }

    for (int t = 0; t < L_DIM; ++t) {
        const unsigned wt = 64u * (unsigned)t;

#pragma unroll
        for (int g = 0; g < 2; ++g) {
            unsigned* ctr = g ? ctrB : ctrA;
            float* hs = g ? hsB : hsA;
            const int b0 = g ? b0B : b0A;
            const size_t ob = (g ? obaseB : obaseA) + (size_t)t * D_DIM;
            float xp = g ? xpB : xpA;

            // ---- wait for this group's previous step ----
            if (t > 0) {
                if (tid == 0) {
                    unsigned v;
                    int spins = 0;
                    while (true) {
                        asm volatile("ld.acquire.gpu.u32 %0, [%1];"
                                     : "=r"(v) : "l"(ctr) : "memory");
                        if (v >= wt) break;
                        if (++spins > 8) __nanosleep(32);
                    }
                }
                __syncthreads();
            }

            // ---- stage h_{t-1}: warp w stages row b0+w ----
            {
                const float* src = (t == 0)
                    ? (h0 + (size_t)(b0 + warp) * D_DIM)
                    : (out + ((size_t)(b0 + warp) * L_DIM + (t - 1)) * D_DIM);
#pragma unroll
                for (int half = 0; half < 2; ++half) {
                    float4 v[4];
#pragma unroll
                    for (int m = 0; m < 4; ++m)
                        v[m] = __ldcg((const float4*)(src + ((half * 4 + m) * 32 + lane) * 4));
#pragma unroll
                    for (int m = 0; m < 4; ++m) {
                        int idx = (half * 4 + m) * 32 + lane;
                        *(float4*)(hs + warp * HROW_F + (idx >> 3) * 36 + (idx & 7) * 4) = v[m];
                    }
                }
            }
            __syncthreads();

            // xp prefetch for this group's next step
            float xp_next = 0.0f;
            if (tid < 128 && t + 1 < L_DIM) xp_next = out[ob + D_DIM];

            // ---- compute: 8 b x 2 j x 32 k per thread (128 ffma2) ----
            u64 acc[8][2];
#pragma unroll
            for (int b = 0; b < 8; ++b) { acc[b][0] = 0ull; acc[b][1] = 0ull; }

#pragma unroll
            for (int b = 0; b < 8; ++b) {
                const ulonglong2* hb = (const ulonglong2*)(hs + b * HROW_F + kc * 36);
#pragma unroll
                for (int i = 0; i < 8; ++i) {
                    ulonglong2 hp = hb[i];
                    ffma2(acc[b][0], hp.x, wreg[0][2 * i]);
                    ffma2(acc[b][1], hp.x, wreg[1][2 * i]);
                    ffma2(acc[b][0], hp.y, wreg[0][2 * i + 1]);
                    ffma2(acc[b][1], hp.y, wreg[1][2 * i + 1]);
                }
            }

#pragma unroll
            for (int b = 0; b < 8; ++b)
#pragma unroll
                for (int jl = 0; jl < 2; ++jl) {
                    float lo, hi;
                    unpack2(acc[b][jl], lo, hi);
                    part[(b * 16 + jq * 2 + jl) * PART_STRIDE + kcs] = lo + hi;
                }

            __syncthreads();

            // ---- reduce (threads 0..127) + tanh + store ----
            if (tid < 128) {
                float s = xp;
                const float* pr = part + (rb * 16 + rj) * PART_STRIDE;
#pragma unroll
                for (int gg = 0; gg < 8; ++gg) {
                    float4 p = *(const float4*)(pr + gg * 4);
                    s += (p.x + p.y) + (p.z + p.w);
                }
                out[ob] = tanhf(s);
            }

            __syncthreads();   // outputs stored; part free for next group

            // ---- arrive ----
            if (t + 1 < L_DIM && tid == 0) {
                asm volatile("red.release.gpu.add.u32 [%0], 1;" :: "l"(ctr) : "memory");
            }

            if (g) xpB = xp_next; else xpA = xp_next;
        }
    }
}

// ---------------------------------------------------------------------------
extern "C" void kernel_launch(void* const* d_in, const int* in_sizes, int n_in,
                              void* d_out, int out_size)
{
    (void)in_sizes; (void)n_in; (void)out_size;
    const float* x  = (const float*)d_in[0];
    const float* h0 = (const float*)d_in[1];
    const float* Wx = (const float*)d_in[2];
    const float* Wh = (const float*)d_in[3];
    float* out = (float*)d_out;

    // phase 1: 3xTF32 tensor-core GEMM (R14 config)
    cudaFuncSetAttribute(gemm_mma_kernel,
                         cudaFuncAttributeMaxDynamicSharedMemorySize,
                         P1_SMEM_BYTES);
    dim3 g1(D_DIM / 128, (B_DIM * L_DIM) / 128);
    gemm_mma_kernel<<<g1, 256, P1_SMEM_BYTES>>>(x, Wx, out);

    // phase 2: persistent recurrence (two-group interleave)
    init_flags_kernel<<<1, 32>>>();
    size_t smem_bytes = (size_t)SMEM2_FLOATS * sizeof(float);
    cudaFuncSetAttribute(rnn_steps_kernel,
                         cudaFuncAttributeMaxDynamicSharedMemorySize,
                         (int)smem_bytes);
    rnn_steps_kernel<<<NB, TPB, smem_bytes>>>(out, h0, Wh);
}